// round 14
// baseline (speedup 1.0000x reference)
#include <cuda_runtime.h>
#include <cuda_fp16.h>
#include <math.h>
#include <stdint.h>

#define H    2048
#define II   4096
#define E    8
#define NTOK 2048
#define GU   (2*II)

#define BM 128
#define BKH 64                          // k-halves per chunk (128 bytes)
#define NS 3

#define STG 16384                       // stage: 128 rows * 128B
#define SMEM_BYTES (2 * NS * STG)       // 98304

// ---------------- scratch ------------------------------------------------------
__device__ int    g_cnt[E];
__device__ int    g_tok[E * NTOK];
__device__ float  g_wslot[E * NTOK];    // routing weight per (expert, slot)
__device__ __align__(16) __half g_xh[(size_t)NTOK * H];
__device__ __align__(16) __half g_mid[(size_t)(E + 1) * NTOK * II];
__device__ __align__(16) __half g_wguT[(size_t)(E + 1) * GU * H];
__device__ __align__(16) __half g_wdnT[(size_t)(E + 1) * H * II];

// ---------------- helpers ------------------------------------------------------
__device__ __forceinline__ uint32_t smem_u32(const void* p) {
    uint32_t a;
    asm("{ .reg .u64 t; cvta.to.shared.u64 t, %1; cvt.u32.u64 %0, t; }" : "=r"(a) : "l"(p));
    return a;
}
__device__ __forceinline__ void mma16(float* c, const uint32_t* a, const uint32_t* b) {
    asm volatile(
        "mma.sync.aligned.m16n8k16.row.col.f32.f16.f16.f32 "
        "{%0,%1,%2,%3}, {%4,%5,%6,%7}, {%8,%9}, {%0,%1,%2,%3};"
        : "+f"(c[0]), "+f"(c[1]), "+f"(c[2]), "+f"(c[3])
        : "r"(a[0]), "r"(a[1]), "r"(a[2]), "r"(a[3]), "r"(b[0]), "r"(b[1]));
}
__device__ __forceinline__ void ldsm4(uint32_t* r, uint32_t addr) {
    asm volatile("ldmatrix.sync.aligned.m8n8.x4.shared.b16 {%0,%1,%2,%3}, [%4];"
        : "=r"(r[0]), "=r"(r[1]), "=r"(r[2]), "=r"(r[3]) : "r"(addr));
}
__device__ __forceinline__ void cpa16(uint32_t dst, const void* src) {
    asm volatile("cp.async.cg.shared.global [%0], [%1], 16;" :: "r"(dst), "l"(src) : "memory");
}
#define CP_COMMIT() asm volatile("cp.async.commit_group;" ::: "memory")
#define CP_WAIT1()  asm volatile("cp.async.wait_group 1;" ::: "memory")
#define CP_WAIT0()  asm volatile("cp.async.wait_group 0;" ::: "memory")

__device__ __forceinline__ float silu(float g) { return g / (1.f + __expf(-g)); }

// ---------------- prepass ------------------------------------------------------
// transpose src[R][C] fp32 (C contig) -> dst[C][R] fp16; 64x64 tiles.
__global__ void __launch_bounds__(256) k_transpose(
    const float* __restrict__ src, __half* __restrict__ dst,
    int R, int C, size_t sseg, size_t dseg)
{
    __shared__ float tile[64][65];
    int seg = blockIdx.z;
    src += (size_t)seg * sseg;
    dst += (size_t)seg * dseg;
    int bc = blockIdx.x * 64, br = blockIdx.y * 64;
    int t = threadIdx.x;
    int q = t & 15, r = t >> 4;
#pragma unroll
    for (int j = 0; j < 4; j++) {
        int row = r + j * 16;
        float4 v = *(const float4*)(src + (size_t)(br + row) * C + bc + q * 4);
        tile[row][q * 4 + 0] = v.x;
        tile[row][q * 4 + 1] = v.y;
        tile[row][q * 4 + 2] = v.z;
        tile[row][q * 4 + 3] = v.w;
    }
    __syncthreads();
#pragma unroll
    for (int j = 0; j < 4; j++) {
        int cl = r + j * 16;
        __half2 w0 = __floats2half2_rn(tile[q * 4 + 0][cl], tile[q * 4 + 1][cl]);
        __half2 w1 = __floats2half2_rn(tile[q * 4 + 2][cl], tile[q * 4 + 3][cl]);
        uint2 u;
        u.x = *(uint32_t*)&w0;
        u.y = *(uint32_t*)&w1;
        *(uint2*)(dst + (size_t)(bc + cl) * R + br + q * 4) = u;
    }
}

// ---------------- small kernels --------------------------------------------------
__global__ void k_zero() { if (threadIdx.x < E) g_cnt[threadIdx.x] = 0; }

__global__ void k_zero_out(float* __restrict__ out) {
    size_t i = ((size_t)blockIdx.x * blockDim.x + threadIdx.x) * 4;
    float4 z = {0.f, 0.f, 0.f, 0.f};
    *(float4*)(out + i) = z;
}

// router + fused fp16 conversion of x (writes g_xh)
__global__ void k_router(const float* __restrict__ x, const float* __restrict__ gate_w) {
    int n = blockIdx.x;
    __shared__ float red[256][E];
    const float* xr = x + (size_t)n * H;
    __half* xh = g_xh + (size_t)n * H;
    float acc[E];
#pragma unroll
    for (int e = 0; e < E; e++) acc[e] = 0.f;
    for (int h = threadIdx.x; h < H; h += 256) {
        float xv = xr[h];
        xh[h] = __float2half_rn(xv);
        const float* gw = gate_w + (size_t)h * E;
#pragma unroll
        for (int e = 0; e < E; e++) acc[e] += xv * gw[e];
    }
#pragma unroll
    for (int e = 0; e < E; e++) red[threadIdx.x][e] = acc[e];
    __syncthreads();
    for (int s = 128; s > 0; s >>= 1) {
        if (threadIdx.x < s) {
#pragma unroll
            for (int e = 0; e < E; e++) red[threadIdx.x][e] += red[threadIdx.x + s][e];
        }
        __syncthreads();
    }
    if (threadIdx.x == 0) {
        float l[E];
#pragma unroll
        for (int e = 0; e < E; e++) l[e] = red[0][e];
        int i0 = 0;
        for (int e = 1; e < E; e++) if (l[e] > l[i0]) i0 = e;
        int i1 = -1;
        for (int e = 0; e < E; e++) {
            if (e == i0) continue;
            if (i1 < 0 || l[e] > l[i1]) i1 = e;
        }
        float m  = fmaxf(l[i0], l[i1]);
        float e0 = expf(l[i0] - m), e1 = expf(l[i1] - m);
        float inv = 1.f / (e0 + e1);
        int s0 = atomicAdd(&g_cnt[i0], 1);
        int s1 = atomicAdd(&g_cnt[i1], 1);
        g_tok[i0 * NTOK + s0] = n;
        g_tok[i1 * NTOK + s1] = n;
        g_wslot[i0 * NTOK + s0] = e0 * inv;
        g_wslot[i1 * NTOK + s1] = e1 * inv;
    }
}

// =================================================================================
// GEMM1: gate_up + SiLU*mul*(routing weight). CTA 128 x 64 out-cols; 8 warps 4mx2n.
// =================================================================================
__global__ void __launch_bounds__(256, 2) k_gateup_tc(const float* dummy)
{
    int seg = blockIdx.z;
    int m0 = blockIdx.y * BM;
    int n0g = blockIdx.x * 64;
    int M; const int* tokp = nullptr;
    if (seg < E) { M = g_cnt[seg]; tokp = g_tok + seg * NTOK; }
    else         { M = NTOK; }
    if (m0 >= M) return;
    const __half* wT = g_wguT + (size_t)seg * GU * H;

    extern __shared__ float sm[];
    uint32_t smbA = smem_u32(sm);
    uint32_t smbB = smbA + NS * STG;

    int tid = threadIdx.x, lane = tid & 31, wid = tid >> 5;
    int wm = wid & 3, wn = wid >> 2;
    int g4 = lane >> 2, l4 = lane & 3;

    int frow = tid >> 1, half = tid & 1;
    int r7f = frow & 7;
    int amr = min(m0 + frow, M - 1);
    const __half* a_src = g_xh + (size_t)((seg < E) ? tokp[amr] : amr) * H + half * 32;
    const __half* b_src = wT + (size_t)((frow < 64) ? (n0g + frow) : (II + n0g + frow - 64)) * H + half * 32;
    uint32_t a_dstrow = smbA + frow * 128;
    uint32_t b_dstrow = smbB + frow * 128;
    uint32_t dq[4];
#pragma unroll
    for (int q = 0; q < 4; q++) dq[q] = 16u * (uint32_t)((half * 4 + q) ^ r7f);

    int lt = lane >> 3, lr = lane & 7;
    uint32_t a_rowb = (uint32_t)(wm * 32 + ((lt & 1) << 3) + lr) * 128;
    int khA = lt >> 1, khB = lt & 1, na = lt >> 1;
    uint32_t xorA[4], xorB[4];
#pragma unroll
    for (int ks = 0; ks < 4; ks++) {
        xorA[ks] = 16u * (uint32_t)((2 * ks + khA) ^ lr);
        xorB[ks] = 16u * (uint32_t)((2 * ks + khB) ^ lr);
    }
    uint32_t b_rowb[4];
#pragma unroll
    for (int p = 0; p < 4; p++) {
        int colb = (p < 2) ? (wn * 32 + (2 * p + na) * 8)
                           : (64 + wn * 32 + (2 * (p - 2) + na) * 8);
        b_rowb[p] = (uint32_t)(colb + lr) * 128;
    }

    float acc[2][8][4];
#pragma unroll
    for (int a = 0; a < 2; a++)
#pragma unroll
        for (int b = 0; b < 8; b++)
#pragma unroll
            for (int c = 0; c < 4; c++) acc[a][b][c] = 0.f;

    const int NCH = H / BKH;   // 32

#define FILL(s, c) do {                                                          \
    int k0 = (c) * BKH;                                                          \
    uint32_t ad = a_dstrow + (s) * STG;                                          \
    uint32_t bd = b_dstrow + (s) * STG;                                          \
    cpa16(ad + dq[0], a_src + k0);       cpa16(ad + dq[1], a_src + k0 + 8);      \
    cpa16(ad + dq[2], a_src + k0 + 16);  cpa16(ad + dq[3], a_src + k0 + 24);     \
    cpa16(bd + dq[0], b_src + k0);       cpa16(bd + dq[1], b_src + k0 + 8);      \
    cpa16(bd + dq[2], b_src + k0 + 16);  cpa16(bd + dq[3], b_src + k0 + 24);     \
} while (0)

    FILL(0, 0); CP_COMMIT();
    FILL(1, 1); CP_COMMIT();

    int st = 0, stf = 2;
    for (int c = 0; c < NCH; c++) {
        CP_WAIT1();
        __syncthreads();
        uint32_t sa = smbA + st * STG;
        uint32_t sb = smbB + st * STG;
#pragma unroll
        for (int ks = 0; ks < 4; ks++) {
            uint32_t af[2][4];
            ldsm4(af[0], sa + a_rowb + xorA[ks]);
            ldsm4(af[1], sa + a_rowb + 2048 + xorA[ks]);
#pragma unroll
            for (int p = 0; p < 4; p++) {
                uint32_t bf[4];
                ldsm4(bf, sb + b_rowb[p] + xorB[ks]);
                mma16(acc[0][2 * p],     af[0], bf);
                mma16(acc[0][2 * p + 1], af[0], bf + 2);
                mma16(acc[1][2 * p],     af[1], bf);
                mma16(acc[1][2 * p + 1], af[1], bf + 2);
            }
        }
        int nf = c + 2;
        if (nf < NCH) FILL(stf, nf);
        CP_COMMIT();
        st  = (st  == 2) ? 0 : st + 1;
        stf = (stf == 2) ? 0 : stf + 1;
    }
    CP_WAIT0();
#undef FILL

    __half* midseg = g_mid + (size_t)seg * NTOK * II;
#pragma unroll
    for (int ma = 0; ma < 2; ma++) {
        int r0 = m0 + wm * 32 + ma * 16 + g4;
        float wA = 1.f, wB = 1.f;
        if (seg < E) {
            if (r0 < M)     wA = g_wslot[seg * NTOK + r0];
            if (r0 + 8 < M) wB = g_wslot[seg * NTOK + r0 + 8];
        }
#pragma unroll
        for (int nn = 0; nn < 4; nn++) {
            int col = n0g + wn * 32 + nn * 8 + l4 * 2;
            float* ga = acc[ma][nn];
            float* ua = acc[ma][nn + 4];
            if (r0 < M) {
                __half2 v = __floats2half2_rn(silu(ga[0]) * ua[0] * wA,
                                              silu(ga[1]) * ua[1] * wA);
                *(__half2*)(midseg + (size_t)r0 * II + col) = v;
            }
            if (r0 + 8 < M) {
                __half2 v = __floats2half2_rn(silu(ga[2]) * ua[2] * wB,
                                              silu(ga[3]) * ua[3] * wB);
                *(__half2*)(midseg + (size_t)(r0 + 8) * II + col) = v;
            }
        }
    }
}

// =================================================================================
// GEMM2: down projection (fp16). CTA 128 x 128; epilogue atomicAdd into out.
// =================================================================================
__global__ void __launch_bounds__(256, 2) k_down_tc(float* __restrict__ out)
{
    int seg = blockIdx.z;
    int m0 = blockIdx.y * BM;
    int n0 = blockIdx.x * 128;
    int M; const int* tokp = nullptr;
    if (seg < E) { M = g_cnt[seg]; tokp = g_tok + seg * NTOK; }
    else         { M = NTOK; }
    if (m0 >= M) return;
    const __half* wT = g_wdnT + (size_t)seg * H * II;

    extern __shared__ float sm[];
    uint32_t smbA = smem_u32(sm);
    uint32_t smbB = smbA + NS * STG;

    int tid = threadIdx.x, lane = tid & 31, wid = tid >> 5;
    int wm = wid & 3, wn = wid >> 2;
    int g4 = lane >> 2, l4 = lane & 3;

    int frow = tid >> 1, half = tid & 1;
    int r7f = frow & 7;
    int amr = min(m0 + frow, M - 1);
    const __half* a_src = g_mid + (size_t)(seg * NTOK + amr) * II + half * 32;
    const __half* b_src = wT + (size_t)(n0 + frow) * II + half * 32;
    uint32_t a_dstrow = smbA + frow * 128;
    uint32_t b_dstrow = smbB + frow * 128;
    uint32_t dq[4];
#pragma unroll
    for (int q = 0; q < 4; q++) dq[q] = 16u * (uint32_t)((half * 4 + q) ^ r7f);

    int lt = lane >> 3, lr = lane & 7;
    uint32_t a_rowb = (uint32_t)(wm * 32 + ((lt & 1) << 3) + lr) * 128;
    int khA = lt >> 1, khB = lt & 1, na = lt >> 1;
    uint32_t xorA[4], xorB[4];
#pragma unroll
    for (int ks = 0; ks < 4; ks++) {
        xorA[ks] = 16u * (uint32_t)((2 * ks + khA) ^ lr);
        xorB[ks] = 16u * (uint32_t)((2 * ks + khB) ^ lr);
    }
    uint32_t b_rowb[4];
#pragma unroll
    for (int p = 0; p < 4; p++) {
        int colb = wn * 64 + (2 * p + na) * 8;
        b_rowb[p] = (uint32_t)(colb + lr) * 128;
    }

    float acc[2][8][4];
#pragma unroll
    for (int a = 0; a < 2; a++)
#pragma unroll
        for (int b = 0; b < 8; b++)
#pragma unroll
            for (int c = 0; c < 4; c++) acc[a][b][c] = 0.f;

    const int NCH = II / BKH;  // 64

#define FILL(s, c) do {                                                          \
    int k0 = (c) * BKH;                                                          \
    uint32_t ad = a_dstrow + (s) * STG;                                          \
    uint32_t bd = b_dstrow + (s) * STG;                                          \
    cpa16(ad + dq[0], a_src + k0);       cpa16(ad + dq[1], a_src + k0 + 8);      \
    cpa16(ad + dq[2], a_src + k0 + 16);  cpa16(ad + dq[3], a_src + k0 + 24);     \
    cpa16(bd + dq[0], b_src + k0);       cpa16(bd + dq[1], b_src + k0 + 8);      \
    cpa16(bd + dq[2], b_src + k0 + 16);  cpa16(bd + dq[3], b_src + k0 + 24);     \
} while (0)

    FILL(0, 0); CP_COMMIT();
    FILL(1, 1); CP_COMMIT();

    int st = 0, stf = 2;
    for (int c = 0; c < NCH; c++) {
        CP_WAIT1();
        __syncthreads();
        uint32_t sa = smbA + st * STG;
        uint32_t sb = smbB + st * STG;
#pragma unroll
        for (int ks = 0; ks < 4; ks++) {
            uint32_t af[2][4];
            ldsm4(af[0], sa + a_rowb + xorA[ks]);
            ldsm4(af[1], sa + a_rowb + 2048 + xorA[ks]);
#pragma unroll
            for (int p = 0; p < 4; p++) {
                uint32_t bf[4];
                ldsm4(bf, sb + b_rowb[p] + xorB[ks]);
                mma16(acc[0][2 * p],     af[0], bf);
                mma16(acc[0][2 * p + 1], af[0], bf + 2);
                mma16(acc[1][2 * p],     af[1], bf);
                mma16(acc[1][2 * p + 1], af[1], bf + 2);
            }
        }
        int nf = c + 2;
        if (nf < NCH) FILL(stf, nf);
        CP_COMMIT();
        st  = (st  == 2) ? 0 : st + 1;
        stf = (stf == 2) ? 0 : stf + 1;
    }
    CP_WAIT0();
#undef FILL

    // epilogue: accumulate into out at the TOKEN row (weights already folded in mid)
#pragma unroll
    for (int ma = 0; ma < 2; ma++) {
        int r0 = m0 + wm * 32 + ma * 16 + g4;
        int tA = 0, tB = 0;
        if (r0 < M)     tA = (seg < E) ? tokp[r0]     : r0;
        if (r0 + 8 < M) tB = (seg < E) ? tokp[r0 + 8] : r0 + 8;
#pragma unroll
        for (int nn = 0; nn < 8; nn++) {
            int col = n0 + wn * 64 + nn * 8 + l4 * 2;
            float* a = acc[ma][nn];
            if (r0 < M) {
                float* p = out + (size_t)tA * H + col;
                atomicAdd(p,     a[0]);
                atomicAdd(p + 1, a[1]);
            }
            if (r0 + 8 < M) {
                float* p = out + (size_t)tB * H + col;
                atomicAdd(p,     a[2]);
                atomicAdd(p + 1, a[3]);
            }
        }
    }
}

// ---------------- launch ----------------------------------------------------------
extern "C" void kernel_launch(void* const* d_in, const int* in_sizes, int n_in,
                              void* d_out, int out_size) {
    const float* x         = (const float*)d_in[0];
    const float* gate_w    = (const float*)d_in[1];
    const float* base_gu   = (const float*)d_in[2];
    const float* base_down = (const float*)d_in[3];
    const float* exp_gu    = (const float*)d_in[4];
    const float* exp_down  = (const float*)d_in[5];
    float* out = (float*)d_out;

    cudaFuncSetAttribute(k_gateup_tc, cudaFuncAttributeMaxDynamicSharedMemorySize, SMEM_BYTES);
    cudaFuncSetAttribute(k_down_tc,   cudaFuncAttributeMaxDynamicSharedMemorySize, SMEM_BYTES);

    __half* wguT_base;  cudaGetSymbolAddress((void**)&wguT_base, g_wguT);
    __half* wdnT_base;  cudaGetSymbolAddress((void**)&wdnT_base, g_wdnT);

    k_zero<<<1, 32>>>();
    k_zero_out<<<(NTOK * H) / (256 * 4), 256>>>(out);
    k_router<<<NTOK, 256>>>(x, gate_w);     // also emits g_xh (fused fp16 convert)
    k_transpose<<<dim3(GU / 64, H / 64, E), 256>>>(exp_gu, wguT_base, H, GU,
                                                   (size_t)H * GU, (size_t)GU * H);
    k_transpose<<<dim3(GU / 64, H / 64, 1), 256>>>(base_gu, wguT_base + (size_t)E * GU * H,
                                                   H, GU, 0, 0);
    k_transpose<<<dim3(H / 64, II / 64, E), 256>>>(exp_down, wdnT_base, II, H,
                                                   (size_t)II * H, (size_t)H * II);
    k_transpose<<<dim3(H / 64, II / 64, 1), 256>>>(base_down, wdnT_base + (size_t)E * H * II,
                                                   II, H, 0, 0);

    k_gateup_tc<<<dim3(II / 64, NTOK / BM, E + 1), 256, SMEM_BYTES>>>(x);
    k_down_tc<<<dim3(H / 128, NTOK / BM, E + 1), 256, SMEM_BYTES>>>(out);
}

// round 15
// speedup vs baseline: 1.0549x; 1.0549x over previous
#include <cuda_runtime.h>
#include <cuda_fp16.h>
#include <math.h>
#include <stdint.h>

#define H    2048
#define II   4096
#define E    8
#define NTOK 2048
#define GU   (2*II)

#define BM 128
#define BKH 64                          // k-halves per chunk (128 bytes)
#define NS 3

#define STG 16384                       // stage: 128 rows * 128B
#define SMEM_BYTES (2 * NS * STG)       // 98304

// ---------------- scratch ------------------------------------------------------
__device__ int    g_cnt[E];
__device__ int    g_tok[E * NTOK];
__device__ int    g_slot[NTOK * 2];
__device__ float  g_w[NTOK * 2];
__device__ __align__(16) __half g_xh[(size_t)NTOK * H];
__device__ __align__(16) __half g_mid[(size_t)(E + 1) * NTOK * II];
__device__ float  g_pout[(size_t)E * NTOK * H];
__device__ __align__(16) __half g_wguT[(size_t)(E + 1) * GU * H];
__device__ __align__(16) __half g_wdnT[(size_t)(E + 1) * H * II];

// ---------------- helpers ------------------------------------------------------
__device__ __forceinline__ uint32_t smem_u32(const void* p) {
    uint32_t a;
    asm("{ .reg .u64 t; cvta.to.shared.u64 t, %1; cvt.u32.u64 %0, t; }" : "=r"(a) : "l"(p));
    return a;
}
__device__ __forceinline__ void mma16(float* c, const uint32_t* a, const uint32_t* b) {
    asm volatile(
        "mma.sync.aligned.m16n8k16.row.col.f32.f16.f16.f32 "
        "{%0,%1,%2,%3}, {%4,%5,%6,%7}, {%8,%9}, {%0,%1,%2,%3};"
        : "+f"(c[0]), "+f"(c[1]), "+f"(c[2]), "+f"(c[3])
        : "r"(a[0]), "r"(a[1]), "r"(a[2]), "r"(a[3]), "r"(b[0]), "r"(b[1]));
}
__device__ __forceinline__ void ldsm4(uint32_t* r, uint32_t addr) {
    asm volatile("ldmatrix.sync.aligned.m8n8.x4.shared.b16 {%0,%1,%2,%3}, [%4];"
        : "=r"(r[0]), "=r"(r[1]), "=r"(r[2]), "=r"(r[3]) : "r"(addr));
}
__device__ __forceinline__ void cpa16(uint32_t dst, const void* src) {
    asm volatile("cp.async.cg.shared.global [%0], [%1], 16;" :: "r"(dst), "l"(src) : "memory");
}
#define CP_COMMIT() asm volatile("cp.async.commit_group;" ::: "memory")
#define CP_WAIT1()  asm volatile("cp.async.wait_group 1;" ::: "memory")
#define CP_WAIT0()  asm volatile("cp.async.wait_group 0;" ::: "memory")

__device__ __forceinline__ float silu(float g) { return g / (1.f + __expf(-g)); }

// ---------------- prepass ------------------------------------------------------
// transpose src[R][C] fp32 (C contig) -> dst[C][R] fp16; 64x64 tiles.
__global__ void __launch_bounds__(256) k_transpose(
    const float* __restrict__ src, __half* __restrict__ dst,
    int R, int C, size_t sseg, size_t dseg)
{
    __shared__ float tile[64][65];
    int seg = blockIdx.z;
    src += (size_t)seg * sseg;
    dst += (size_t)seg * dseg;
    int bc = blockIdx.x * 64, br = blockIdx.y * 64;
    int t = threadIdx.x;
    int q = t & 15, r = t >> 4;
#pragma unroll
    for (int j = 0; j < 4; j++) {
        int row = r + j * 16;
        float4 v = *(const float4*)(src + (size_t)(br + row) * C + bc + q * 4);
        tile[row][q * 4 + 0] = v.x;
        tile[row][q * 4 + 1] = v.y;
        tile[row][q * 4 + 2] = v.z;
        tile[row][q * 4 + 3] = v.w;
    }
    __syncthreads();
#pragma unroll
    for (int j = 0; j < 4; j++) {
        int cl = r + j * 16;
        __half2 w0 = __floats2half2_rn(tile[q * 4 + 0][cl], tile[q * 4 + 1][cl]);
        __half2 w1 = __floats2half2_rn(tile[q * 4 + 2][cl], tile[q * 4 + 3][cl]);
        uint2 u;
        u.x = *(uint32_t*)&w0;
        u.y = *(uint32_t*)&w1;
        *(uint2*)(dst + (size_t)(bc + cl) * R + br + q * 4) = u;
    }
}

// ---------------- small kernels --------------------------------------------------
__global__ void k_zero() { if (threadIdx.x < E) g_cnt[threadIdx.x] = 0; }

// router + fused fp16 conversion of x (writes g_xh)
__global__ void k_router(const float* __restrict__ x, const float* __restrict__ gate_w) {
    int n = blockIdx.x;
    __shared__ float red[256][E];
    const float* xr = x + (size_t)n * H;
    __half* xh = g_xh + (size_t)n * H;
    float acc[E];
#pragma unroll
    for (int e = 0; e < E; e++) acc[e] = 0.f;
    for (int h = threadIdx.x; h < H; h += 256) {
        float xv = xr[h];
        xh[h] = __float2half_rn(xv);
        const float* gw = gate_w + (size_t)h * E;
#pragma unroll
        for (int e = 0; e < E; e++) acc[e] += xv * gw[e];
    }
#pragma unroll
    for (int e = 0; e < E; e++) red[threadIdx.x][e] = acc[e];
    __syncthreads();
    for (int s = 128; s > 0; s >>= 1) {
        if (threadIdx.x < s) {
#pragma unroll
            for (int e = 0; e < E; e++) red[threadIdx.x][e] += red[threadIdx.x + s][e];
        }
        __syncthreads();
    }
    if (threadIdx.x == 0) {
        float l[E];
#pragma unroll
        for (int e = 0; e < E; e++) l[e] = red[0][e];
        int i0 = 0;
        for (int e = 1; e < E; e++) if (l[e] > l[i0]) i0 = e;
        int i1 = -1;
        for (int e = 0; e < E; e++) {
            if (e == i0) continue;
            if (i1 < 0 || l[e] > l[i1]) i1 = e;
        }
        float m  = fmaxf(l[i0], l[i1]);
        float e0 = expf(l[i0] - m), e1 = expf(l[i1] - m);
        float inv = 1.f / (e0 + e1);
        int s0 = atomicAdd(&g_cnt[i0], 1);
        int s1 = atomicAdd(&g_cnt[i1], 1);
        g_tok[i0 * NTOK + s0] = n;
        g_tok[i1 * NTOK + s1] = n;
        g_slot[n * 2 + 0] = i0 * NTOK + s0;
        g_slot[n * 2 + 1] = i1 * NTOK + s1;
        g_w[n * 2 + 0] = e0 * inv;
        g_w[n * 2 + 1] = e1 * inv;
    }
}

__global__ void k_combine(float* __restrict__ out) {
    int n = blockIdx.y;
    int h4 = (blockIdx.x * blockDim.x + threadIdx.x) * 4;
    int s0 = g_slot[n * 2 + 0], s1 = g_slot[n * 2 + 1];
    float w0 = g_w[n * 2 + 0],  w1 = g_w[n * 2 + 1];
    float* op = out + (size_t)n * H + h4;
    float4 o  = *(float4*)op;
    float4 p0 = *(const float4*)(g_pout + (size_t)s0 * H + h4);
    float4 p1 = *(const float4*)(g_pout + (size_t)s1 * H + h4);
    o.x += w0 * p0.x + w1 * p1.x;
    o.y += w0 * p0.y + w1 * p1.y;
    o.z += w0 * p0.z + w1 * p1.z;
    o.w += w0 * p0.w + w1 * p1.w;
    *(float4*)op = o;
}

// =================================================================================
// GEMM1: gate_up + SiLU*mul (fp16 m16n8k16). CTA 128 x 64 out-cols; 8 warps 4mx2n.
// B-stationary schedule: blockIdx.x = m-tile (fastest) so co-resident CTAs share B.
// grid (NTOK/BM, II/64, E+1).
// =================================================================================
__global__ void __launch_bounds__(256, 2) k_gateup_tc(const float* dummy)
{
    int seg = blockIdx.z;
    int m0 = blockIdx.x * BM;
    int n0g = blockIdx.y * 64;
    int M; const int* tokp = nullptr;
    if (seg < E) { M = g_cnt[seg]; tokp = g_tok + seg * NTOK; }
    else         { M = NTOK; }
    if (m0 >= M) return;
    const __half* wT = g_wguT + (size_t)seg * GU * H;

    extern __shared__ float sm[];
    uint32_t smbA = smem_u32(sm);
    uint32_t smbB = smbA + NS * STG;

    int tid = threadIdx.x, lane = tid & 31, wid = tid >> 5;
    int wm = wid & 3, wn = wid >> 2;
    int g4 = lane >> 2, l4 = lane & 3;

    int frow = tid >> 1, half = tid & 1;
    int r7f = frow & 7;
    int amr = min(m0 + frow, M - 1);
    const __half* a_src = g_xh + (size_t)((seg < E) ? tokp[amr] : amr) * H + half * 32;
    const __half* b_src = wT + (size_t)((frow < 64) ? (n0g + frow) : (II + n0g + frow - 64)) * H + half * 32;
    uint32_t a_dstrow = smbA + frow * 128;
    uint32_t b_dstrow = smbB + frow * 128;
    uint32_t dq[4];
#pragma unroll
    for (int q = 0; q < 4; q++) dq[q] = 16u * (uint32_t)((half * 4 + q) ^ r7f);

    int lt = lane >> 3, lr = lane & 7;
    uint32_t a_rowb = (uint32_t)(wm * 32 + ((lt & 1) << 3) + lr) * 128;
    int khA = lt >> 1, khB = lt & 1, na = lt >> 1;
    uint32_t xorA[4], xorB[4];
#pragma unroll
    for (int ks = 0; ks < 4; ks++) {
        xorA[ks] = 16u * (uint32_t)((2 * ks + khA) ^ lr);
        xorB[ks] = 16u * (uint32_t)((2 * ks + khB) ^ lr);
    }
    uint32_t b_rowb[4];
#pragma unroll
    for (int p = 0; p < 4; p++) {
        int colb = (p < 2) ? (wn * 32 + (2 * p + na) * 8)
                           : (64 + wn * 32 + (2 * (p - 2) + na) * 8);
        b_rowb[p] = (uint32_t)(colb + lr) * 128;
    }

    float acc[2][8][4];
#pragma unroll
    for (int a = 0; a < 2; a++)
#pragma unroll
        for (int b = 0; b < 8; b++)
#pragma unroll
            for (int c = 0; c < 4; c++) acc[a][b][c] = 0.f;

    const int NCH = H / BKH;   // 32

#define FILL(s, c) do {                                                          \
    int k0 = (c) * BKH;                                                          \
    uint32_t ad = a_dstrow + (s) * STG;                                          \
    uint32_t bd = b_dstrow + (s) * STG;                                          \
    cpa16(ad + dq[0], a_src + k0);       cpa16(ad + dq[1], a_src + k0 + 8);      \
    cpa16(ad + dq[2], a_src + k0 + 16);  cpa16(ad + dq[3], a_src + k0 + 24);     \
    cpa16(bd + dq[0], b_src + k0);       cpa16(bd + dq[1], b_src + k0 + 8);      \
    cpa16(bd + dq[2], b_src + k0 + 16);  cpa16(bd + dq[3], b_src + k0 + 24);     \
} while (0)

    FILL(0, 0); CP_COMMIT();
    FILL(1, 1); CP_COMMIT();

    int st = 0, stf = 2;
    for (int c = 0; c < NCH; c++) {
        CP_WAIT1();
        __syncthreads();
        uint32_t sa = smbA + st * STG;
        uint32_t sb = smbB + st * STG;
#pragma unroll
        for (int ks = 0; ks < 4; ks++) {
            uint32_t af[2][4];
            ldsm4(af[0], sa + a_rowb + xorA[ks]);
            ldsm4(af[1], sa + a_rowb + 2048 + xorA[ks]);
#pragma unroll
            for (int p = 0; p < 4; p++) {
                uint32_t bf[4];
                ldsm4(bf, sb + b_rowb[p] + xorB[ks]);
                mma16(acc[0][2 * p],     af[0], bf);
                mma16(acc[0][2 * p + 1], af[0], bf + 2);
                mma16(acc[1][2 * p],     af[1], bf);
                mma16(acc[1][2 * p + 1], af[1], bf + 2);
            }
        }
        int nf = c + 2;
        if (nf < NCH) FILL(stf, nf);
        CP_COMMIT();
        st  = (st  == 2) ? 0 : st + 1;
        stf = (stf == 2) ? 0 : stf + 1;
    }
    CP_WAIT0();
#undef FILL

    __half* midseg = g_mid + (size_t)seg * NTOK * II;
#pragma unroll
    for (int ma = 0; ma < 2; ma++) {
        int r0 = m0 + wm * 32 + ma * 16 + g4;
#pragma unroll
        for (int nn = 0; nn < 4; nn++) {
            int col = n0g + wn * 32 + nn * 8 + l4 * 2;
            float* ga = acc[ma][nn];
            float* ua = acc[ma][nn + 4];
            if (r0 < M) {
                __half2 v = __floats2half2_rn(silu(ga[0]) * ua[0], silu(ga[1]) * ua[1]);
                *(__half2*)(midseg + (size_t)r0 * II + col) = v;
            }
            if (r0 + 8 < M) {
                __half2 v = __floats2half2_rn(silu(ga[2]) * ua[2], silu(ga[3]) * ua[3]);
                *(__half2*)(midseg + (size_t)(r0 + 8) * II + col) = v;
            }
        }
    }
}

// =================================================================================
// GEMM2: down projection (fp16). CTA 128 x 128; 8 warps 4mx2n, warp 32x64.
// B-stationary: grid (NTOK/BM, H/128, E+1).
// =================================================================================
__global__ void __launch_bounds__(256, 2) k_down_tc(float* __restrict__ out)
{
    int seg = blockIdx.z;
    int m0 = blockIdx.x * BM;
    int n0 = blockIdx.y * 128;
    int M;
    if (seg < E) M = g_cnt[seg];
    else         M = NTOK;
    if (m0 >= M) return;
    const __half* wT = g_wdnT + (size_t)seg * H * II;

    extern __shared__ float sm[];
    uint32_t smbA = smem_u32(sm);
    uint32_t smbB = smbA + NS * STG;

    int tid = threadIdx.x, lane = tid & 31, wid = tid >> 5;
    int wm = wid & 3, wn = wid >> 2;
    int g4 = lane >> 2, l4 = lane & 3;

    int frow = tid >> 1, half = tid & 1;
    int r7f = frow & 7;
    int amr = min(m0 + frow, M - 1);
    const __half* a_src = g_mid + (size_t)(seg * NTOK + amr) * II + half * 32;
    const __half* b_src = wT + (size_t)(n0 + frow) * II + half * 32;
    uint32_t a_dstrow = smbA + frow * 128;
    uint32_t b_dstrow = smbB + frow * 128;
    uint32_t dq[4];
#pragma unroll
    for (int q = 0; q < 4; q++) dq[q] = 16u * (uint32_t)((half * 4 + q) ^ r7f);

    int lt = lane >> 3, lr = lane & 7;
    uint32_t a_rowb = (uint32_t)(wm * 32 + ((lt & 1) << 3) + lr) * 128;
    int khA = lt >> 1, khB = lt & 1, na = lt >> 1;
    uint32_t xorA[4], xorB[4];
#pragma unroll
    for (int ks = 0; ks < 4; ks++) {
        xorA[ks] = 16u * (uint32_t)((2 * ks + khA) ^ lr);
        xorB[ks] = 16u * (uint32_t)((2 * ks + khB) ^ lr);
    }
    uint32_t b_rowb[4];
#pragma unroll
    for (int p = 0; p < 4; p++) {
        int colb = wn * 64 + (2 * p + na) * 8;
        b_rowb[p] = (uint32_t)(colb + lr) * 128;
    }

    float acc[2][8][4];
#pragma unroll
    for (int a = 0; a < 2; a++)
#pragma unroll
        for (int b = 0; b < 8; b++)
#pragma unroll
            for (int c = 0; c < 4; c++) acc[a][b][c] = 0.f;

    const int NCH = II / BKH;  // 64

#define FILL(s, c) do {                                                          \
    int k0 = (c) * BKH;                                                          \
    uint32_t ad = a_dstrow + (s) * STG;                                          \
    uint32_t bd = b_dstrow + (s) * STG;                                          \
    cpa16(ad + dq[0], a_src + k0);       cpa16(ad + dq[1], a_src + k0 + 8);      \
    cpa16(ad + dq[2], a_src + k0 + 16);  cpa16(ad + dq[3], a_src + k0 + 24);     \
    cpa16(bd + dq[0], b_src + k0);       cpa16(bd + dq[1], b_src + k0 + 8);      \
    cpa16(bd + dq[2], b_src + k0 + 16);  cpa16(bd + dq[3], b_src + k0 + 24);     \
} while (0)

    FILL(0, 0); CP_COMMIT();
    FILL(1, 1); CP_COMMIT();

    int st = 0, stf = 2;
    for (int c = 0; c < NCH; c++) {
        CP_WAIT1();
        __syncthreads();
        uint32_t sa = smbA + st * STG;
        uint32_t sb = smbB + st * STG;
#pragma unroll
        for (int ks = 0; ks < 4; ks++) {
            uint32_t af[2][4];
            ldsm4(af[0], sa + a_rowb + xorA[ks]);
            ldsm4(af[1], sa + a_rowb + 2048 + xorA[ks]);
#pragma unroll
            for (int p = 0; p < 4; p++) {
                uint32_t bf[4];
                ldsm4(bf, sb + b_rowb[p] + xorB[ks]);
                mma16(acc[0][2 * p],     af[0], bf);
                mma16(acc[0][2 * p + 1], af[0], bf + 2);
                mma16(acc[1][2 * p],     af[1], bf);
                mma16(acc[1][2 * p + 1], af[1], bf + 2);
            }
        }
        int nf = c + 2;
        if (nf < NCH) FILL(stf, nf);
        CP_COMMIT();
        st  = (st  == 2) ? 0 : st + 1;
        stf = (stf == 2) ? 0 : stf + 1;
    }
    CP_WAIT0();
#undef FILL

    float* C = (seg < E) ? (g_pout + (size_t)seg * NTOK * H) : out;
#pragma unroll
    for (int ma = 0; ma < 2; ma++) {
        int r0 = m0 + wm * 32 + ma * 16 + g4;
#pragma unroll
        for (int nn = 0; nn < 8; nn++) {
            int col = n0 + wn * 64 + nn * 8 + l4 * 2;
            float* a = acc[ma][nn];
            if (r0 < M) {
                float2 v = { a[0], a[1] };
                *(float2*)(C + (size_t)r0 * H + col) = v;
            }
            if (r0 + 8 < M) {
                float2 v = { a[2], a[3] };
                *(float2*)(C + (size_t)(r0 + 8) * H + col) = v;
            }
        }
    }
}

// ---------------- launch ----------------------------------------------------------
extern "C" void kernel_launch(void* const* d_in, const int* in_sizes, int n_in,
                              void* d_out, int out_size) {
    const float* x         = (const float*)d_in[0];
    const float* gate_w    = (const float*)d_in[1];
    const float* base_gu   = (const float*)d_in[2];
    const float* base_down = (const float*)d_in[3];
    const float* exp_gu    = (const float*)d_in[4];
    const float* exp_down  = (const float*)d_in[5];
    float* out = (float*)d_out;

    cudaFuncSetAttribute(k_gateup_tc, cudaFuncAttributeMaxDynamicSharedMemorySize, SMEM_BYTES);
    cudaFuncSetAttribute(k_down_tc,   cudaFuncAttributeMaxDynamicSharedMemorySize, SMEM_BYTES);

    __half* wguT_base;  cudaGetSymbolAddress((void**)&wguT_base, g_wguT);
    __half* wdnT_base;  cudaGetSymbolAddress((void**)&wdnT_base, g_wdnT);

    k_zero<<<1, 32>>>();
    k_router<<<NTOK, 256>>>(x, gate_w);     // also emits g_xh (fused fp16 convert)
    k_transpose<<<dim3(GU / 64, H / 64, E), 256>>>(exp_gu, wguT_base, H, GU,
                                                   (size_t)H * GU, (size_t)GU * H);
    k_transpose<<<dim3(GU / 64, H / 64, 1), 256>>>(base_gu, wguT_base + (size_t)E * GU * H,
                                                   H, GU, 0, 0);
    k_transpose<<<dim3(H / 64, II / 64, E), 256>>>(exp_down, wdnT_base, II, H,
                                                   (size_t)II * H, (size_t)H * II);
    k_transpose<<<dim3(H / 64, II / 64, 1), 256>>>(base_down, wdnT_base + (size_t)E * H * II,
                                                   II, H, 0, 0);

    k_gateup_tc<<<dim3(NTOK / BM, II / 64, E + 1), 256, SMEM_BYTES>>>(x);
    k_down_tc<<<dim3(NTOK / BM, H / 128, E + 1), 256, SMEM_BYTES>>>(out);
    k_combine<<<dim3(H / (4 * 128), NTOK), 128>>>(out);
}

// round 16
// speedup vs baseline: 1.0658x; 1.0104x over previous
#include <cuda_runtime.h>
#include <cuda_fp16.h>
#include <math.h>
#include <stdint.h>

#define H    2048
#define II   4096
#define E    8
#define NTOK 2048
#define GU   (2*II)

#define BM 128
#define BKH 64                          // k-halves per chunk (128 bytes)
#define NS 3

#define STG 16384                       // stage: 128 rows * 128B
#define SMEM_BYTES (2 * NS * STG)       // 98304

// ---------------- scratch ------------------------------------------------------
__device__ int    g_cnt[E];
__device__ int    g_tok[E * NTOK];
__device__ int    g_slot[NTOK * 2];
__device__ float  g_w[NTOK * 2];
__device__ __align__(16) __half g_xh[(size_t)NTOK * H];
__device__ __align__(16) __half g_mid[(size_t)(E + 1) * NTOK * II];
__device__ float  g_pout[(size_t)E * NTOK * H];
__device__ __align__(16) __half g_wguT[(size_t)(E + 1) * GU * H];
__device__ __align__(16) __half g_wdnT[(size_t)(E + 1) * H * II];

// ---------------- helpers ------------------------------------------------------
__device__ __forceinline__ uint32_t smem_u32(const void* p) {
    uint32_t a;
    asm("{ .reg .u64 t; cvta.to.shared.u64 t, %1; cvt.u32.u64 %0, t; }" : "=r"(a) : "l"(p));
    return a;
}
__device__ __forceinline__ void mma16(float* c, const uint32_t* a, const uint32_t* b) {
    asm volatile(
        "mma.sync.aligned.m16n8k16.row.col.f32.f16.f16.f32 "
        "{%0,%1,%2,%3}, {%4,%5,%6,%7}, {%8,%9}, {%0,%1,%2,%3};"
        : "+f"(c[0]), "+f"(c[1]), "+f"(c[2]), "+f"(c[3])
        : "r"(a[0]), "r"(a[1]), "r"(a[2]), "r"(a[3]), "r"(b[0]), "r"(b[1]));
}
__device__ __forceinline__ void ldsm4(uint32_t* r, uint32_t addr) {
    asm volatile("ldmatrix.sync.aligned.m8n8.x4.shared.b16 {%0,%1,%2,%3}, [%4];"
        : "=r"(r[0]), "=r"(r[1]), "=r"(r[2]), "=r"(r[3]) : "r"(addr));
}
__device__ __forceinline__ void cpa16(uint32_t dst, const void* src) {
    asm volatile("cp.async.cg.shared.global [%0], [%1], 16;" :: "r"(dst), "l"(src) : "memory");
}
#define CP_COMMIT() asm volatile("cp.async.commit_group;" ::: "memory")
#define CP_WAIT1()  asm volatile("cp.async.wait_group 1;" ::: "memory")
#define CP_WAIT0()  asm volatile("cp.async.wait_group 0;" ::: "memory")

__device__ __forceinline__ float silu(float g) { return g / (1.f + __expf(-g)); }

// ---------------- prepass ------------------------------------------------------
// transpose src[R][C] fp32 (C contig) -> dst[C][R] fp16; 64x64 tiles.
__global__ void __launch_bounds__(256) k_transpose(
    const float* __restrict__ src, __half* __restrict__ dst,
    int R, int C, size_t sseg, size_t dseg)
{
    __shared__ float tile[64][65];
    int seg = blockIdx.z;
    src += (size_t)seg * sseg;
    dst += (size_t)seg * dseg;
    int bc = blockIdx.x * 64, br = blockIdx.y * 64;
    int t = threadIdx.x;
    int q = t & 15, r = t >> 4;
#pragma unroll
    for (int j = 0; j < 4; j++) {
        int row = r + j * 16;
        float4 v = *(const float4*)(src + (size_t)(br + row) * C + bc + q * 4);
        tile[row][q * 4 + 0] = v.x;
        tile[row][q * 4 + 1] = v.y;
        tile[row][q * 4 + 2] = v.z;
        tile[row][q * 4 + 3] = v.w;
    }
    __syncthreads();
#pragma unroll
    for (int j = 0; j < 4; j++) {
        int cl = r + j * 16;
        __half2 w0 = __floats2half2_rn(tile[q * 4 + 0][cl], tile[q * 4 + 1][cl]);
        __half2 w1 = __floats2half2_rn(tile[q * 4 + 2][cl], tile[q * 4 + 3][cl]);
        uint2 u;
        u.x = *(uint32_t*)&w0;
        u.y = *(uint32_t*)&w1;
        *(uint2*)(dst + (size_t)(bc + cl) * R + br + q * 4) = u;
    }
}

// ---------------- small kernels --------------------------------------------------
__global__ void k_zero() { if (threadIdx.x < E) g_cnt[threadIdx.x] = 0; }

// router + fused fp16 conversion of x (writes g_xh)
__global__ void k_router(const float* __restrict__ x, const float* __restrict__ gate_w) {
    int n = blockIdx.x;
    __shared__ float red[256][E];
    const float* xr = x + (size_t)n * H;
    __half* xh = g_xh + (size_t)n * H;
    float acc[E];
#pragma unroll
    for (int e = 0; e < E; e++) acc[e] = 0.f;
    for (int h = threadIdx.x; h < H; h += 256) {
        float xv = xr[h];
        xh[h] = __float2half_rn(xv);
        const float* gw = gate_w + (size_t)h * E;
#pragma unroll
        for (int e = 0; e < E; e++) acc[e] += xv * gw[e];
    }
#pragma unroll
    for (int e = 0; e < E; e++) red[threadIdx.x][e] = acc[e];
    __syncthreads();
    for (int s = 128; s > 0; s >>= 1) {
        if (threadIdx.x < s) {
#pragma unroll
            for (int e = 0; e < E; e++) red[threadIdx.x][e] += red[threadIdx.x + s][e];
        }
        __syncthreads();
    }
    if (threadIdx.x == 0) {
        float l[E];
#pragma unroll
        for (int e = 0; e < E; e++) l[e] = red[0][e];
        int i0 = 0;
        for (int e = 1; e < E; e++) if (l[e] > l[i0]) i0 = e;
        int i1 = -1;
        for (int e = 0; e < E; e++) {
            if (e == i0) continue;
            if (i1 < 0 || l[e] > l[i1]) i1 = e;
        }
        float m  = fmaxf(l[i0], l[i1]);
        float e0 = expf(l[i0] - m), e1 = expf(l[i1] - m);
        float inv = 1.f / (e0 + e1);
        int s0 = atomicAdd(&g_cnt[i0], 1);
        int s1 = atomicAdd(&g_cnt[i1], 1);
        g_tok[i0 * NTOK + s0] = n;
        g_tok[i1 * NTOK + s1] = n;
        g_slot[n * 2 + 0] = i0 * NTOK + s0;
        g_slot[n * 2 + 1] = i1 * NTOK + s1;
        g_w[n * 2 + 0] = e0 * inv;
        g_w[n * 2 + 1] = e1 * inv;
    }
}

__global__ void k_combine(float* __restrict__ out) {
    int n = blockIdx.y;
    int h4 = (blockIdx.x * blockDim.x + threadIdx.x) * 4;
    int s0 = g_slot[n * 2 + 0], s1 = g_slot[n * 2 + 1];
    float w0 = g_w[n * 2 + 0],  w1 = g_w[n * 2 + 1];
    float* op = out + (size_t)n * H + h4;
    float4 o  = *(float4*)op;
    float4 p0 = *(const float4*)(g_pout + (size_t)s0 * H + h4);
    float4 p1 = *(const float4*)(g_pout + (size_t)s1 * H + h4);
    o.x += w0 * p0.x + w1 * p1.x;
    o.y += w0 * p0.y + w1 * p1.y;
    o.z += w0 * p0.z + w1 * p1.z;
    o.w += w0 * p0.w + w1 * p1.w;
    *(float4*)op = o;
}

// =================================================================================
// GEMM1: gate_up + SiLU*mul (fp16 m16n8k16). CTA 128 x 64 out-cols; 8 warps 4mx2n.
// B-stationary: grid (NTOK/BM, II/64, E+1).
// =================================================================================
__global__ void __launch_bounds__(256, 2) k_gateup_tc(const float* dummy)
{
    int seg = blockIdx.z;
    int m0 = blockIdx.x * BM;
    int n0g = blockIdx.y * 64;
    int M; const int* tokp = nullptr;
    if (seg < E) { M = g_cnt[seg]; tokp = g_tok + seg * NTOK; }
    else         { M = NTOK; }
    if (m0 >= M) return;
    const __half* wT = g_wguT + (size_t)seg * GU * H;

    extern __shared__ float sm[];
    uint32_t smbA = smem_u32(sm);
    uint32_t smbB = smbA + NS * STG;

    int tid = threadIdx.x, lane = tid & 31, wid = tid >> 5;
    int wm = wid & 3, wn = wid >> 2;
    int g4 = lane >> 2, l4 = lane & 3;

    int frow = tid >> 1, half = tid & 1;
    int r7f = frow & 7;
    int amr = min(m0 + frow, M - 1);
    const __half* a_src = g_xh + (size_t)((seg < E) ? tokp[amr] : amr) * H + half * 32;
    const __half* b_src = wT + (size_t)((frow < 64) ? (n0g + frow) : (II + n0g + frow - 64)) * H + half * 32;
    uint32_t a_dstrow = smbA + frow * 128;
    uint32_t b_dstrow = smbB + frow * 128;
    uint32_t dq[4];
#pragma unroll
    for (int q = 0; q < 4; q++) dq[q] = 16u * (uint32_t)((half * 4 + q) ^ r7f);

    int lt = lane >> 3, lr = lane & 7;
    uint32_t a_rowb = (uint32_t)(wm * 32 + ((lt & 1) << 3) + lr) * 128;
    int khA = lt >> 1, khB = lt & 1, na = lt >> 1;
    uint32_t xorA[4], xorB[4];
#pragma unroll
    for (int ks = 0; ks < 4; ks++) {
        xorA[ks] = 16u * (uint32_t)((2 * ks + khA) ^ lr);
        xorB[ks] = 16u * (uint32_t)((2 * ks + khB) ^ lr);
    }
    uint32_t b_rowb[4];
#pragma unroll
    for (int p = 0; p < 4; p++) {
        int colb = (p < 2) ? (wn * 32 + (2 * p + na) * 8)
                           : (64 + wn * 32 + (2 * (p - 2) + na) * 8);
        b_rowb[p] = (uint32_t)(colb + lr) * 128;
    }

    float acc[2][8][4];
#pragma unroll
    for (int a = 0; a < 2; a++)
#pragma unroll
        for (int b = 0; b < 8; b++)
#pragma unroll
            for (int c = 0; c < 4; c++) acc[a][b][c] = 0.f;

    const int NCH = H / BKH;   // 32

#define FILL(s, c) do {                                                          \
    int k0 = (c) * BKH;                                                          \
    uint32_t ad = a_dstrow + (s) * STG;                                          \
    uint32_t bd = b_dstrow + (s) * STG;                                          \
    cpa16(ad + dq[0], a_src + k0);       cpa16(ad + dq[1], a_src + k0 + 8);      \
    cpa16(ad + dq[2], a_src + k0 + 16);  cpa16(ad + dq[3], a_src + k0 + 24);     \
    cpa16(bd + dq[0], b_src + k0);       cpa16(bd + dq[1], b_src + k0 + 8);      \
    cpa16(bd + dq[2], b_src + k0 + 16);  cpa16(bd + dq[3], b_src + k0 + 24);     \
} while (0)

    FILL(0, 0); CP_COMMIT();
    FILL(1, 1); CP_COMMIT();

    int st = 0, stf = 2;
    for (int c = 0; c < NCH; c++) {
        CP_WAIT1();
        __syncthreads();
        uint32_t sa = smbA + st * STG;
        uint32_t sb = smbB + st * STG;
#pragma unroll
        for (int ks = 0; ks < 4; ks++) {
            uint32_t af[2][4];
            ldsm4(af[0], sa + a_rowb + xorA[ks]);
            ldsm4(af[1], sa + a_rowb + 2048 + xorA[ks]);
#pragma unroll
            for (int p = 0; p < 4; p++) {
                uint32_t bf[4];
                ldsm4(bf, sb + b_rowb[p] + xorB[ks]);
                mma16(acc[0][2 * p],     af[0], bf);
                mma16(acc[0][2 * p + 1], af[0], bf + 2);
                mma16(acc[1][2 * p],     af[1], bf);
                mma16(acc[1][2 * p + 1], af[1], bf + 2);
            }
        }
        int nf = c + 2;
        if (nf < NCH) FILL(stf, nf);
        CP_COMMIT();
        st  = (st  == 2) ? 0 : st + 1;
        stf = (stf == 2) ? 0 : stf + 1;
    }
    CP_WAIT0();
#undef FILL

    __half* midseg = g_mid + (size_t)seg * NTOK * II;
#pragma unroll
    for (int ma = 0; ma < 2; ma++) {
        int r0 = m0 + wm * 32 + ma * 16 + g4;
#pragma unroll
        for (int nn = 0; nn < 4; nn++) {
            int col = n0g + wn * 32 + nn * 8 + l4 * 2;
            float* ga = acc[ma][nn];
            float* ua = acc[ma][nn + 4];
            if (r0 < M) {
                __half2 v = __floats2half2_rn(silu(ga[0]) * ua[0], silu(ga[1]) * ua[1]);
                *(__half2*)(midseg + (size_t)r0 * II + col) = v;
            }
            if (r0 + 8 < M) {
                __half2 v = __floats2half2_rn(silu(ga[2]) * ua[2], silu(ga[3]) * ua[3]);
                *(__half2*)(midseg + (size_t)(r0 + 8) * II + col) = v;
            }
        }
    }
}

// =================================================================================
// GEMM2: down projection (fp16). CTA 128 x 128; 8 warps 4mx2n, warp 32x64.
// B-stationary: grid (NTOK/BM, H/128, E+1).
// =================================================================================
__global__ void __launch_bounds__(256, 2) k_down_tc(float* __restrict__ out)
{
    int seg = blockIdx.z;
    int m0 = blockIdx.x * BM;
    int n0 = blockIdx.y * 128;
    int M;
    if (seg < E) M = g_cnt[seg];
    else         M = NTOK;
    if (m0 >= M) return;
    const __half* wT = g_wdnT + (size_t)seg * H * II;

    extern __shared__ float sm[];
    uint32_t smbA = smem_u32(sm);
    uint32_t smbB = smbA + NS * STG;

    int tid = threadIdx.x, lane = tid & 31, wid = tid >> 5;
    int wm = wid & 3, wn = wid >> 2;
    int g4 = lane >> 2, l4 = lane & 3;

    int frow = tid >> 1, half = tid & 1;
    int r7f = frow & 7;
    int amr = min(m0 + frow, M - 1);
    const __half* a_src = g_mid + (size_t)(seg * NTOK + amr) * II + half * 32;
    const __half* b_src = wT + (size_t)(n0 + frow) * II + half * 32;
    uint32_t a_dstrow = smbA + frow * 128;
    uint32_t b_dstrow = smbB + frow * 128;
    uint32_t dq[4];
#pragma unroll
    for (int q = 0; q < 4; q++) dq[q] = 16u * (uint32_t)((half * 4 + q) ^ r7f);

    int lt = lane >> 3, lr = lane & 7;
    uint32_t a_rowb = (uint32_t)(wm * 32 + ((lt & 1) << 3) + lr) * 128;
    int khA = lt >> 1, khB = lt & 1, na = lt >> 1;
    uint32_t xorA[4], xorB[4];
#pragma unroll
    for (int ks = 0; ks < 4; ks++) {
        xorA[ks] = 16u * (uint32_t)((2 * ks + khA) ^ lr);
        xorB[ks] = 16u * (uint32_t)((2 * ks + khB) ^ lr);
    }
    uint32_t b_rowb[4];
#pragma unroll
    for (int p = 0; p < 4; p++) {
        int colb = wn * 64 + (2 * p + na) * 8;
        b_rowb[p] = (uint32_t)(colb + lr) * 128;
    }

    float acc[2][8][4];
#pragma unroll
    for (int a = 0; a < 2; a++)
#pragma unroll
        for (int b = 0; b < 8; b++)
#pragma unroll
            for (int c = 0; c < 4; c++) acc[a][b][c] = 0.f;

    const int NCH = II / BKH;  // 64

#define FILL(s, c) do {                                                          \
    int k0 = (c) * BKH;                                                          \
    uint32_t ad = a_dstrow + (s) * STG;                                          \
    uint32_t bd = b_dstrow + (s) * STG;                                          \
    cpa16(ad + dq[0], a_src + k0);       cpa16(ad + dq[1], a_src + k0 + 8);      \
    cpa16(ad + dq[2], a_src + k0 + 16);  cpa16(ad + dq[3], a_src + k0 + 24);     \
    cpa16(bd + dq[0], b_src + k0);       cpa16(bd + dq[1], b_src + k0 + 8);      \
    cpa16(bd + dq[2], b_src + k0 + 16);  cpa16(bd + dq[3], b_src + k0 + 24);     \
} while (0)

    FILL(0, 0); CP_COMMIT();
    FILL(1, 1); CP_COMMIT();

    int st = 0, stf = 2;
    for (int c = 0; c < NCH; c++) {
        CP_WAIT1();
        __syncthreads();
        uint32_t sa = smbA + st * STG;
        uint32_t sb = smbB + st * STG;
#pragma unroll
        for (int ks = 0; ks < 4; ks++) {
            uint32_t af[2][4];
            ldsm4(af[0], sa + a_rowb + xorA[ks]);
            ldsm4(af[1], sa + a_rowb + 2048 + xorA[ks]);
#pragma unroll
            for (int p = 0; p < 4; p++) {
                uint32_t bf[4];
                ldsm4(bf, sb + b_rowb[p] + xorB[ks]);
                mma16(acc[0][2 * p],     af[0], bf);
                mma16(acc[0][2 * p + 1], af[0], bf + 2);
                mma16(acc[1][2 * p],     af[1], bf);
                mma16(acc[1][2 * p + 1], af[1], bf + 2);
            }
        }
        int nf = c + 2;
        if (nf < NCH) FILL(stf, nf);
        CP_COMMIT();
        st  = (st  == 2) ? 0 : st + 1;
        stf = (stf == 2) ? 0 : stf + 1;
    }
    CP_WAIT0();
#undef FILL

    float* C = (seg < E) ? (g_pout + (size_t)seg * NTOK * H) : out;
#pragma unroll
    for (int ma = 0; ma < 2; ma++) {
        int r0 = m0 + wm * 32 + ma * 16 + g4;
#pragma unroll
        for (int nn = 0; nn < 8; nn++) {
            int col = n0 + wn * 64 + nn * 8 + l4 * 2;
            float* a = acc[ma][nn];
            if (r0 < M) {
                float2 v = { a[0], a[1] };
                *(float2*)(C + (size_t)r0 * H + col) = v;
            }
            if (r0 + 8 < M) {
                float2 v = { a[2], a[3] };
                *(float2*)(C + (size_t)(r0 + 8) * H + col) = v;
            }
        }
    }
}

// ---------------- launch ----------------------------------------------------------
extern "C" void kernel_launch(void* const* d_in, const int* in_sizes, int n_in,
                              void* d_out, int out_size) {
    const float* x         = (const float*)d_in[0];
    const float* gate_w    = (const float*)d_in[1];
    const float* base_gu   = (const float*)d_in[2];
    const float* base_down = (const float*)d_in[3];
    const float* exp_gu    = (const float*)d_in[4];
    const float* exp_down  = (const float*)d_in[5];
    float* out = (float*)d_out;

    cudaFuncSetAttribute(k_gateup_tc, cudaFuncAttributeMaxDynamicSharedMemorySize, SMEM_BYTES);
    cudaFuncSetAttribute(k_down_tc,   cudaFuncAttributeMaxDynamicSharedMemorySize, SMEM_BYTES);

    __half* wguT_base;  cudaGetSymbolAddress((void**)&wguT_base, g_wguT);
    __half* wdnT_base;  cudaGetSymbolAddress((void**)&wdnT_base, g_wdnT);

    // fork a side stream so the down-weight prepass overlaps the gateup GEMM
    cudaStream_t s1;
    cudaStreamCreateWithFlags(&s1, cudaStreamNonBlocking);
    cudaEvent_t e0, e1;
    cudaEventCreateWithFlags(&e0, cudaEventDisableTiming);
    cudaEventCreateWithFlags(&e1, cudaEventDisableTiming);

    k_zero<<<1, 32>>>();
    cudaEventRecord(e0, 0);
    cudaStreamWaitEvent(s1, e0, 0);

    // side stream: down-projection weight transposes (consumed only by k_down_tc)
    k_transpose<<<dim3(H / 64, II / 64, E), 256, 0, s1>>>(exp_down, wdnT_base, II, H,
                                                          (size_t)II * H, (size_t)H * II);
    k_transpose<<<dim3(H / 64, II / 64, 1), 256, 0, s1>>>(base_down,
                                                          wdnT_base + (size_t)E * H * II,
                                                          II, H, 0, 0);
    cudaEventRecord(e1, s1);

    // main stream: router + gate_up weight prep + gateup GEMM
    k_router<<<NTOK, 256>>>(x, gate_w);     // also emits g_xh (fused fp16 convert)
    k_transpose<<<dim3(GU / 64, H / 64, E), 256>>>(exp_gu, wguT_base, H, GU,
                                                   (size_t)H * GU, (size_t)GU * H);
    k_transpose<<<dim3(GU / 64, H / 64, 1), 256>>>(base_gu, wguT_base + (size_t)E * GU * H,
                                                   H, GU, 0, 0);
    k_gateup_tc<<<dim3(NTOK / BM, II / 64, E + 1), 256, SMEM_BYTES>>>(x);

    cudaStreamWaitEvent(0, e1, 0);          // join: down GEMM needs g_wdnT
    k_down_tc<<<dim3(NTOK / BM, H / 128, E + 1), 256, SMEM_BYTES>>>(out);
    k_combine<<<dim3(H / (4 * 128), NTOK), 128>>>(out);
}

// round 17
// speedup vs baseline: 1.0778x; 1.0113x over previous
#include <cuda_runtime.h>
#include <cuda_fp16.h>
#include <math.h>
#include <stdint.h>

#define H    2048
#define II   4096
#define E    8
#define NTOK 2048
#define GU   (2*II)

#define BM 128
#define BKH 64                          // k-halves per chunk (128 bytes)
#define NS 3

#define STG 16384                       // stage: 128 rows * 128B
#define SMEM_BYTES (2 * NS * STG)       // 98304

// ---------------- scratch ------------------------------------------------------
__device__ int    g_cnt[E];
__device__ int    g_tok[E * NTOK];
__device__ int    g_slot[NTOK * 2];
__device__ float  g_w[NTOK * 2];
__device__ __align__(16) __half g_xh[(size_t)NTOK * H];
__device__ __align__(16) __half g_mid[(size_t)(E + 1) * NTOK * II];
__device__ float  g_pout[(size_t)E * NTOK * H];
__device__ __align__(16) __half g_wguT[(size_t)(E + 1) * GU * H];
__device__ __align__(16) __half g_wdnT[(size_t)(E + 1) * H * II];

// ---------------- helpers ------------------------------------------------------
__device__ __forceinline__ uint32_t smem_u32(const void* p) {
    uint32_t a;
    asm("{ .reg .u64 t; cvta.to.shared.u64 t, %1; cvt.u32.u64 %0, t; }" : "=r"(a) : "l"(p));
    return a;
}
__device__ __forceinline__ void mma16(float* c, const uint32_t* a, const uint32_t* b) {
    asm volatile(
        "mma.sync.aligned.m16n8k16.row.col.f32.f16.f16.f32 "
        "{%0,%1,%2,%3}, {%4,%5,%6,%7}, {%8,%9}, {%0,%1,%2,%3};"
        : "+f"(c[0]), "+f"(c[1]), "+f"(c[2]), "+f"(c[3])
        : "r"(a[0]), "r"(a[1]), "r"(a[2]), "r"(a[3]), "r"(b[0]), "r"(b[1]));
}
__device__ __forceinline__ void ldsm4(uint32_t* r, uint32_t addr) {
    asm volatile("ldmatrix.sync.aligned.m8n8.x4.shared.b16 {%0,%1,%2,%3}, [%4];"
        : "=r"(r[0]), "=r"(r[1]), "=r"(r[2]), "=r"(r[3]) : "r"(addr));
}
__device__ __forceinline__ void cpa16(uint32_t dst, const void* src) {
    asm volatile("cp.async.cg.shared.global [%0], [%1], 16;" :: "r"(dst), "l"(src) : "memory");
}
#define CP_COMMIT() asm volatile("cp.async.commit_group;" ::: "memory")
#define CP_WAIT1()  asm volatile("cp.async.wait_group 1;" ::: "memory")
#define CP_WAIT0()  asm volatile("cp.async.wait_group 0;" ::: "memory")

__device__ __forceinline__ float silu(float g) { return g / (1.f + __expf(-g)); }

// ---------------- prepass ------------------------------------------------------
// transpose src[R][C] fp32 (C contig) -> dst[C][R] fp16; 64x64 tiles.
__global__ void __launch_bounds__(256) k_transpose(
    const float* __restrict__ src, __half* __restrict__ dst,
    int R, int C, size_t sseg, size_t dseg)
{
    __shared__ float tile[64][65];
    int seg = blockIdx.z;
    src += (size_t)seg * sseg;
    dst += (size_t)seg * dseg;
    int bc = blockIdx.x * 64, br = blockIdx.y * 64;
    int t = threadIdx.x;
    int q = t & 15, r = t >> 4;
#pragma unroll
    for (int j = 0; j < 4; j++) {
        int row = r + j * 16;
        float4 v = *(const float4*)(src + (size_t)(br + row) * C + bc + q * 4);
        tile[row][q * 4 + 0] = v.x;
        tile[row][q * 4 + 1] = v.y;
        tile[row][q * 4 + 2] = v.z;
        tile[row][q * 4 + 3] = v.w;
    }
    __syncthreads();
#pragma unroll
    for (int j = 0; j < 4; j++) {
        int cl = r + j * 16;
        __half2 w0 = __floats2half2_rn(tile[q * 4 + 0][cl], tile[q * 4 + 1][cl]);
        __half2 w1 = __floats2half2_rn(tile[q * 4 + 2][cl], tile[q * 4 + 3][cl]);
        uint2 u;
        u.x = *(uint32_t*)&w0;
        u.y = *(uint32_t*)&w1;
        *(uint2*)(dst + (size_t)(bc + cl) * R + br + q * 4) = u;
    }
}

// ---------------- small kernels --------------------------------------------------
__global__ void k_zero() { if (threadIdx.x < E) g_cnt[threadIdx.x] = 0; }

// router (vectorized) + fused fp16 conversion of x. One token per block, 256 thr.
__global__ void __launch_bounds__(256) k_router(const float* __restrict__ x,
                                                const float* __restrict__ gate_w) {
    int n = blockIdx.x;
    int tid = threadIdx.x, lane = tid & 31, wrp = tid >> 5;
    const float* xr = x + (size_t)n * H;
    __half* xh = g_xh + (size_t)n * H;
    __shared__ float red[8][E];

    int h0 = tid * 8;
    float4 xa = *(const float4*)(xr + h0);
    float4 xb = *(const float4*)(xr + h0 + 4);
    // fused fp16 copy (one 16B store of 8 halves)
    __half2 p0 = __floats2half2_rn(xa.x, xa.y);
    __half2 p1 = __floats2half2_rn(xa.z, xa.w);
    __half2 p2 = __floats2half2_rn(xb.x, xb.y);
    __half2 p3 = __floats2half2_rn(xb.z, xb.w);
    uint4 pk = { *(uint32_t*)&p0, *(uint32_t*)&p1, *(uint32_t*)&p2, *(uint32_t*)&p3 };
    *(uint4*)(xh + h0) = pk;

    float xv[8] = { xa.x, xa.y, xa.z, xa.w, xb.x, xb.y, xb.z, xb.w };
    float acc[E];
#pragma unroll
    for (int e = 0; e < E; e++) acc[e] = 0.f;
#pragma unroll
    for (int j = 0; j < 8; j++) {
        const float4* gwr = (const float4*)(gate_w + (size_t)(h0 + j) * E);
        float4 g0 = gwr[0], g1 = gwr[1];
        acc[0] += xv[j] * g0.x;  acc[1] += xv[j] * g0.y;
        acc[2] += xv[j] * g0.z;  acc[3] += xv[j] * g0.w;
        acc[4] += xv[j] * g1.x;  acc[5] += xv[j] * g1.y;
        acc[6] += xv[j] * g1.z;  acc[7] += xv[j] * g1.w;
    }
    // warp reduce each of the 8 accumulators
#pragma unroll
    for (int e = 0; e < E; e++) {
#pragma unroll
        for (int s = 16; s > 0; s >>= 1)
            acc[e] += __shfl_down_sync(0xFFFFFFFFu, acc[e], s);
    }
    if (lane == 0) {
#pragma unroll
        for (int e = 0; e < E; e++) red[wrp][e] = acc[e];
    }
    __syncthreads();
    if (tid == 0) {
        float l[E];
#pragma unroll
        for (int e = 0; e < E; e++) {
            float s = red[0][e];
#pragma unroll
            for (int w2 = 1; w2 < 8; w2++) s += red[w2][e];
            l[e] = s;
        }
        int i0 = 0;
        for (int e = 1; e < E; e++) if (l[e] > l[i0]) i0 = e;
        int i1 = -1;
        for (int e = 0; e < E; e++) {
            if (e == i0) continue;
            if (i1 < 0 || l[e] > l[i1]) i1 = e;
        }
        float m  = fmaxf(l[i0], l[i1]);
        float e0 = expf(l[i0] - m), e1 = expf(l[i1] - m);
        float inv = 1.f / (e0 + e1);
        int s0 = atomicAdd(&g_cnt[i0], 1);
        int s1 = atomicAdd(&g_cnt[i1], 1);
        g_tok[i0 * NTOK + s0] = n;
        g_tok[i1 * NTOK + s1] = n;
        g_slot[n * 2 + 0] = i0 * NTOK + s0;
        g_slot[n * 2 + 1] = i1 * NTOK + s1;
        g_w[n * 2 + 0] = e0 * inv;
        g_w[n * 2 + 1] = e1 * inv;
    }
}

__global__ void k_combine(float* __restrict__ out) {
    int n = blockIdx.y;
    int h4 = (blockIdx.x * blockDim.x + threadIdx.x) * 4;
    int s0 = g_slot[n * 2 + 0], s1 = g_slot[n * 2 + 1];
    float w0 = g_w[n * 2 + 0],  w1 = g_w[n * 2 + 1];
    float* op = out + (size_t)n * H + h4;
    float4 o  = *(float4*)op;
    float4 p0 = *(const float4*)(g_pout + (size_t)s0 * H + h4);
    float4 p1 = *(const float4*)(g_pout + (size_t)s1 * H + h4);
    o.x += w0 * p0.x + w1 * p1.x;
    o.y += w0 * p0.y + w1 * p1.y;
    o.z += w0 * p0.z + w1 * p1.z;
    o.w += w0 * p0.w + w1 * p1.w;
    *(float4*)op = o;
}

// =================================================================================
// GEMM1: gate_up + SiLU*mul (fp16 m16n8k16). CTA 128 x 64 out-cols; 8 warps 4mx2n.
// B-stationary: grid (NTOK/BM, II/64, E+1).
// =================================================================================
__global__ void __launch_bounds__(256, 2) k_gateup_tc(const float* dummy)
{
    int seg = blockIdx.z;
    int m0 = blockIdx.x * BM;
    int n0g = blockIdx.y * 64;
    int M; const int* tokp = nullptr;
    if (seg < E) { M = g_cnt[seg]; tokp = g_tok + seg * NTOK; }
    else         { M = NTOK; }
    if (m0 >= M) return;
    const __half* wT = g_wguT + (size_t)seg * GU * H;

    extern __shared__ float sm[];
    uint32_t smbA = smem_u32(sm);
    uint32_t smbB = smbA + NS * STG;

    int tid = threadIdx.x, lane = tid & 31, wid = tid >> 5;
    int wm = wid & 3, wn = wid >> 2;
    int g4 = lane >> 2, l4 = lane & 3;

    int frow = tid >> 1, half = tid & 1;
    int r7f = frow & 7;
    int amr = min(m0 + frow, M - 1);
    const __half* a_src = g_xh + (size_t)((seg < E) ? tokp[amr] : amr) * H + half * 32;
    const __half* b_src = wT + (size_t)((frow < 64) ? (n0g + frow) : (II + n0g + frow - 64)) * H + half * 32;
    uint32_t a_dstrow = smbA + frow * 128;
    uint32_t b_dstrow = smbB + frow * 128;
    uint32_t dq[4];
#pragma unroll
    for (int q = 0; q < 4; q++) dq[q] = 16u * (uint32_t)((half * 4 + q) ^ r7f);

    int lt = lane >> 3, lr = lane & 7;
    uint32_t a_rowb = (uint32_t)(wm * 32 + ((lt & 1) << 3) + lr) * 128;
    int khA = lt >> 1, khB = lt & 1, na = lt >> 1;
    uint32_t xorA[4], xorB[4];
#pragma unroll
    for (int ks = 0; ks < 4; ks++) {
        xorA[ks] = 16u * (uint32_t)((2 * ks + khA) ^ lr);
        xorB[ks] = 16u * (uint32_t)((2 * ks + khB) ^ lr);
    }
    uint32_t b_rowb[4];
#pragma unroll
    for (int p = 0; p < 4; p++) {
        int colb = (p < 2) ? (wn * 32 + (2 * p + na) * 8)
                           : (64 + wn * 32 + (2 * (p - 2) + na) * 8);
        b_rowb[p] = (uint32_t)(colb + lr) * 128;
    }

    float acc[2][8][4];
#pragma unroll
    for (int a = 0; a < 2; a++)
#pragma unroll
        for (int b = 0; b < 8; b++)
#pragma unroll
            for (int c = 0; c < 4; c++) acc[a][b][c] = 0.f;

    const int NCH = H / BKH;   // 32

#define FILL(s, c) do {                                                          \
    int k0 = (c) * BKH;                                                          \
    uint32_t ad = a_dstrow + (s) * STG;                                          \
    uint32_t bd = b_dstrow + (s) * STG;                                          \
    cpa16(ad + dq[0], a_src + k0);       cpa16(ad + dq[1], a_src + k0 + 8);      \
    cpa16(ad + dq[2], a_src + k0 + 16);  cpa16(ad + dq[3], a_src + k0 + 24);     \
    cpa16(bd + dq[0], b_src + k0);       cpa16(bd + dq[1], b_src + k0 + 8);      \
    cpa16(bd + dq[2], b_src + k0 + 16);  cpa16(bd + dq[3], b_src + k0 + 24);     \
} while (0)

    FILL(0, 0); CP_COMMIT();
    FILL(1, 1); CP_COMMIT();

    int st = 0, stf = 2;
    for (int c = 0; c < NCH; c++) {
        CP_WAIT1();
        __syncthreads();
        uint32_t sa = smbA + st * STG;
        uint32_t sb = smbB + st * STG;
#pragma unroll
        for (int ks = 0; ks < 4; ks++) {
            uint32_t af[2][4];
            ldsm4(af[0], sa + a_rowb + xorA[ks]);
            ldsm4(af[1], sa + a_rowb + 2048 + xorA[ks]);
#pragma unroll
            for (int p = 0; p < 4; p++) {
                uint32_t bf[4];
                ldsm4(bf, sb + b_rowb[p] + xorB[ks]);
                mma16(acc[0][2 * p],     af[0], bf);
                mma16(acc[0][2 * p + 1], af[0], bf + 2);
                mma16(acc[1][2 * p],     af[1], bf);
                mma16(acc[1][2 * p + 1], af[1], bf + 2);
            }
        }
        int nf = c + 2;
        if (nf < NCH) FILL(stf, nf);
        CP_COMMIT();
        st  = (st  == 2) ? 0 : st + 1;
        stf = (stf == 2) ? 0 : stf + 1;
    }
    CP_WAIT0();
#undef FILL

    __half* midseg = g_mid + (size_t)seg * NTOK * II;
#pragma unroll
    for (int ma = 0; ma < 2; ma++) {
        int r0 = m0 + wm * 32 + ma * 16 + g4;
#pragma unroll
        for (int nn = 0; nn < 4; nn++) {
            int col = n0g + wn * 32 + nn * 8 + l4 * 2;
            float* ga = acc[ma][nn];
            float* ua = acc[ma][nn + 4];
            if (r0 < M) {
                __half2 v = __floats2half2_rn(silu(ga[0]) * ua[0], silu(ga[1]) * ua[1]);
                *(__half2*)(midseg + (size_t)r0 * II + col) = v;
            }
            if (r0 + 8 < M) {
                __half2 v = __floats2half2_rn(silu(ga[2]) * ua[2], silu(ga[3]) * ua[3]);
                *(__half2*)(midseg + (size_t)(r0 + 8) * II + col) = v;
            }
        }
    }
}

// =================================================================================
// GEMM2: down projection (fp16). CTA 128 x 128; 8 warps 4mx2n, warp 32x64.
// B-stationary: grid (NTOK/BM, H/128, E+1).
// =================================================================================
__global__ void __launch_bounds__(256, 2) k_down_tc(float* __restrict__ out)
{
    int seg = blockIdx.z;
    int m0 = blockIdx.x * BM;
    int n0 = blockIdx.y * 128;
    int M;
    if (seg < E) M = g_cnt[seg];
    else         M = NTOK;
    if (m0 >= M) return;
    const __half* wT = g_wdnT + (size_t)seg * H * II;

    extern __shared__ float sm[];
    uint32_t smbA = smem_u32(sm);
    uint32_t smbB = smbA + NS * STG;

    int tid = threadIdx.x, lane = tid & 31, wid = tid >> 5;
    int wm = wid & 3, wn = wid >> 2;
    int g4 = lane >> 2, l4 = lane & 3;

    int frow = tid >> 1, half = tid & 1;
    int r7f = frow & 7;
    int amr = min(m0 + frow, M - 1);
    const __half* a_src = g_mid + (size_t)(seg * NTOK + amr) * II + half * 32;
    const __half* b_src = wT + (size_t)(n0 + frow) * II + half * 32;
    uint32_t a_dstrow = smbA + frow * 128;
    uint32_t b_dstrow = smbB + frow * 128;
    uint32_t dq[4];
#pragma unroll
    for (int q = 0; q < 4; q++) dq[q] = 16u * (uint32_t)((half * 4 + q) ^ r7f);

    int lt = lane >> 3, lr = lane & 7;
    uint32_t a_rowb = (uint32_t)(wm * 32 + ((lt & 1) << 3) + lr) * 128;
    int khA = lt >> 1, khB = lt & 1, na = lt >> 1;
    uint32_t xorA[4], xorB[4];
#pragma unroll
    for (int ks = 0; ks < 4; ks++) {
        xorA[ks] = 16u * (uint32_t)((2 * ks + khA) ^ lr);
        xorB[ks] = 16u * (uint32_t)((2 * ks + khB) ^ lr);
    }
    uint32_t b_rowb[4];
#pragma unroll
    for (int p = 0; p < 4; p++) {
        int colb = wn * 64 + (2 * p + na) * 8;
        b_rowb[p] = (uint32_t)(colb + lr) * 128;
    }

    float acc[2][8][4];
#pragma unroll
    for (int a = 0; a < 2; a++)
#pragma unroll
        for (int b = 0; b < 8; b++)
#pragma unroll
            for (int c = 0; c < 4; c++) acc[a][b][c] = 0.f;

    const int NCH = II / BKH;  // 64

#define FILL(s, c) do {                                                          \
    int k0 = (c) * BKH;                                                          \
    uint32_t ad = a_dstrow + (s) * STG;                                          \
    uint32_t bd = b_dstrow + (s) * STG;                                          \
    cpa16(ad + dq[0], a_src + k0);       cpa16(ad + dq[1], a_src + k0 + 8);      \
    cpa16(ad + dq[2], a_src + k0 + 16);  cpa16(ad + dq[3], a_src + k0 + 24);     \
    cpa16(bd + dq[0], b_src + k0);       cpa16(bd + dq[1], b_src + k0 + 8);      \
    cpa16(bd + dq[2], b_src + k0 + 16);  cpa16(bd + dq[3], b_src + k0 + 24);     \
} while (0)

    FILL(0, 0); CP_COMMIT();
    FILL(1, 1); CP_COMMIT();

    int st = 0, stf = 2;
    for (int c = 0; c < NCH; c++) {
        CP_WAIT1();
        __syncthreads();
        uint32_t sa = smbA + st * STG;
        uint32_t sb = smbB + st * STG;
#pragma unroll
        for (int ks = 0; ks < 4; ks++) {
            uint32_t af[2][4];
            ldsm4(af[0], sa + a_rowb + xorA[ks]);
            ldsm4(af[1], sa + a_rowb + 2048 + xorA[ks]);
#pragma unroll
            for (int p = 0; p < 4; p++) {
                uint32_t bf[4];
                ldsm4(bf, sb + b_rowb[p] + xorB[ks]);
                mma16(acc[0][2 * p],     af[0], bf);
                mma16(acc[0][2 * p + 1], af[0], bf + 2);
                mma16(acc[1][2 * p],     af[1], bf);
                mma16(acc[1][2 * p + 1], af[1], bf + 2);
            }
        }
        int nf = c + 2;
        if (nf < NCH) FILL(stf, nf);
        CP_COMMIT();
        st  = (st  == 2) ? 0 : st + 1;
        stf = (stf == 2) ? 0 : stf + 1;
    }
    CP_WAIT0();
#undef FILL

    float* C = (seg < E) ? (g_pout + (size_t)seg * NTOK * H) : out;
#pragma unroll
    for (int ma = 0; ma < 2; ma++) {
        int r0 = m0 + wm * 32 + ma * 16 + g4;
#pragma unroll
        for (int nn = 0; nn < 8; nn++) {
            int col = n0 + wn * 64 + nn * 8 + l4 * 2;
            float* a = acc[ma][nn];
            if (r0 < M) {
                float2 v = { a[0], a[1] };
                *(float2*)(C + (size_t)r0 * H + col) = v;
            }
            if (r0 + 8 < M) {
                float2 v = { a[2], a[3] };
                *(float2*)(C + (size_t)(r0 + 8) * H + col) = v;
            }
        }
    }
}

// ---------------- launch ----------------------------------------------------------
extern "C" void kernel_launch(void* const* d_in, const int* in_sizes, int n_in,
                              void* d_out, int out_size) {
    const float* x         = (const float*)d_in[0];
    const float* gate_w    = (const float*)d_in[1];
    const float* base_gu   = (const float*)d_in[2];
    const float* base_down = (const float*)d_in[3];
    const float* exp_gu    = (const float*)d_in[4];
    const float* exp_down  = (const float*)d_in[5];
    float* out = (float*)d_out;

    cudaFuncSetAttribute(k_gateup_tc, cudaFuncAttributeMaxDynamicSharedMemorySize, SMEM_BYTES);
    cudaFuncSetAttribute(k_down_tc,   cudaFuncAttributeMaxDynamicSharedMemorySize, SMEM_BYTES);

    __half* wguT_base;  cudaGetSymbolAddress((void**)&wguT_base, g_wguT);
    __half* wdnT_base;  cudaGetSymbolAddress((void**)&wdnT_base, g_wdnT);

    // side stream: router + down-weight transposes (both off the gateup critical path)
    cudaStream_t s1;
    cudaStreamCreateWithFlags(&s1, cudaStreamNonBlocking);
    cudaEvent_t e0, e_r, e1;
    cudaEventCreateWithFlags(&e0,  cudaEventDisableTiming);
    cudaEventCreateWithFlags(&e_r, cudaEventDisableTiming);
    cudaEventCreateWithFlags(&e1,  cudaEventDisableTiming);

    k_zero<<<1, 32>>>();
    cudaEventRecord(e0, 0);
    cudaStreamWaitEvent(s1, e0, 0);

    // s1: router (needs g_cnt zeroed), then down transposes
    k_router<<<NTOK, 256, 0, s1>>>(x, gate_w);
    cudaEventRecord(e_r, s1);
    k_transpose<<<dim3(H / 64, II / 64, E), 256, 0, s1>>>(exp_down, wdnT_base, II, H,
                                                          (size_t)II * H, (size_t)H * II);
    k_transpose<<<dim3(H / 64, II / 64, 1), 256, 0, s1>>>(base_down,
                                                          wdnT_base + (size_t)E * H * II,
                                                          II, H, 0, 0);
    cudaEventRecord(e1, s1);

    // main: gate_up weight transposes (independent of router)
    k_transpose<<<dim3(GU / 64, H / 64, E), 256>>>(exp_gu, wguT_base, H, GU,
                                                   (size_t)H * GU, (size_t)GU * H);
    k_transpose<<<dim3(GU / 64, H / 64, 1), 256>>>(base_gu, wguT_base + (size_t)E * GU * H,
                                                   H, GU, 0, 0);

    cudaStreamWaitEvent(0, e_r, 0);         // gateup needs router outputs (g_cnt/g_tok/g_xh)
    k_gateup_tc<<<dim3(NTOK / BM, II / 64, E + 1), 256, SMEM_BYTES>>>(x);

    cudaStreamWaitEvent(0, e1, 0);          // down GEMM needs g_wdnT
    k_down_tc<<<dim3(NTOK / BM, H / 128, E + 1), 256, SMEM_BYTES>>>(out);
    k_combine<<<dim3(H / (4 * 128), NTOK), 128>>>(out);
}